// round 9
// baseline (speedup 1.0000x reference)
#include <cuda_runtime.h>
#include <math.h>
#include <stdint.h>

// NTXentLoss: B=2048, P=16, N=128, D=512 (fp32).
// R9: cp.async.bulk (UBLKCP) per-warp double-buffered SMEM ring.
//     Loads fully decoupled from compute: lane 0 issues a 2KB bulk copy per
//     row completing on a warp-private mbarrier; warp computes the other
//     buffer from SMEM meanwhile. Registers freed -> 6 blocks/SM (75% occ),
//     96KB in flight per SM. Valid-only rows + pos row, deferred epilogue.

#define DDIM 512
#define D4 (DDIM / 4)
#define THREADS 256
#define NWARPS (THREADS / 32)   // 8
#define TEMP_INV 10.0f
#define COS_EPS 1e-8f
#define ROW_BYTES 2048

// scratch (no cudaMalloc allowed)
__device__ float g_loss[4096];
__device__ unsigned int g_count = 0;

__device__ __forceinline__ uint32_t smem_u32(const void* p) {
    uint32_t a;
    asm("{ .reg .u64 t; cvta.to.shared.u64 t, %1; cvt.u32.u64 %0, t; }"
        : "=r"(a) : "l"(p));
    return a;
}

__device__ __forceinline__ void mbar_init(uint32_t mbar, uint32_t cnt) {
    asm volatile("mbarrier.init.shared.b64 [%0], %1;" :: "r"(mbar), "r"(cnt) : "memory");
}

__device__ __forceinline__ void mbar_expect_tx(uint32_t mbar, uint32_t bytes) {
    asm volatile("mbarrier.arrive.expect_tx.shared.b64 _, [%0], %1;"
                 :: "r"(mbar), "r"(bytes) : "memory");
}

__device__ __forceinline__ void bulk_copy_g2s(uint32_t dst, const void* src,
                                              uint32_t bytes, uint32_t mbar) {
    asm volatile(
        "cp.async.bulk.shared::cluster.global.mbarrier::complete_tx::bytes "
        "[%0], [%1], %2, [%3];"
        :: "r"(dst), "l"(src), "r"(bytes), "r"(mbar) : "memory");
}

__device__ __forceinline__ void mbar_wait(uint32_t mbar, uint32_t phase) {
    asm volatile(
        "{\n\t.reg .pred P;\n\t"
        "W_%=:\n\t"
        "mbarrier.try_wait.parity.acquire.cta.shared::cta.b64 P, [%0], %1, 0x989680;\n\t"
        "@P bra.uni D_%=;\n\t"
        "bra.uni W_%=;\n\t"
        "D_%=:\n\t}"
        :: "r"(mbar), "r"(phase) : "memory");
}

__device__ __forceinline__ float warpReduceSum(float v) {
#pragma unroll
    for (int o = 16; o; o >>= 1) v += __shfl_down_sync(0xffffffffu, v, o);
    return v;
}

__device__ __forceinline__ float warpReduceMax(float v) {
#pragma unroll
    for (int o = 16; o; o >>= 1) v = fmaxf(v, __shfl_down_sync(0xffffffffu, v, o));
    return v;
}

__device__ __forceinline__ float blockReduceSum(float v, float* sbuf) {
    int lane = threadIdx.x & 31, wid = threadIdx.x >> 5;
    v = warpReduceSum(v);
    if (lane == 0) sbuf[wid] = v;
    __syncthreads();
    v = (threadIdx.x < NWARPS) ? sbuf[threadIdx.x] : 0.0f;
    if (wid == 0) {
#pragma unroll
        for (int o = NWARPS / 2; o; o >>= 1) v += __shfl_down_sync(0xffffffffu, v, o);
    }
    return v;
}

__device__ __forceinline__ float blockReduceMax(float v, float* sbuf) {
    int lane = threadIdx.x & 31, wid = threadIdx.x >> 5;
    v = warpReduceMax(v);
    if (lane == 0) sbuf[wid] = v;
    __syncthreads();
    v = (threadIdx.x < NWARPS) ? sbuf[threadIdx.x] : -INFINITY;
    if (wid == 0) {
#pragma unroll
        for (int o = NWARPS / 2; o; o >>= 1) v = fmaxf(v, __shfl_down_sync(0xffffffffu, v, o));
    }
    return v;
}

__global__ void __launch_bounds__(THREADS)
ntxent_main_kernel(const float* __restrict__ target,
                   const float* __restrict__ positives,
                   const float* __restrict__ negatives,
                   const int* __restrict__ pos_idx,
                   const int* __restrict__ neg_mask,
                   float* __restrict__ out,
                   int B, int P, int N) {
    const int b = blockIdx.x;
    const int tid = threadIdx.x;
    const int lane = tid & 31;
    const int w = tid >> 5;

    __shared__ __align__(128) char s_ring[NWARPS][2][ROW_BYTES];  // 32KB
    __shared__ __align__(8) unsigned long long s_mbar[NWARPS][2];
    __shared__ float4 s_tgt[D4];      // 2KB
    __shared__ float s_dot[132];
    __shared__ float s_q[132];
    __shared__ int   s_valid[132];
    __shared__ int   s_wcnt[NWARPS];
    __shared__ float s_red[NWARPS];
    __shared__ float s_bcast[4];
    __shared__ int   s_islast;

    // --- mbarrier init (warp-private pairs) ---
    if (lane == 0) {
        mbar_init(smem_u32(&s_mbar[w][0]), 1);
        mbar_init(smem_u32(&s_mbar[w][1]), 1);
    }

    // --- compact valid negative indices (deterministic prefix via ballot) ---
    int mvalid = 0;
    if (tid < N) mvalid = (neg_mask[(size_t)b * N + tid] != 0);
    unsigned bal = __ballot_sync(0xffffffffu, mvalid);
    if (lane == 0) s_wcnt[w] = __popc(bal);

    // --- target row -> SMEM, |t|^2 partial ---
    float tq = 0.0f;
    if (tid < D4) {
        float4 tv = ((const float4*)(target + (size_t)b * DDIM))[tid];
        s_tgt[tid] = tv;
        tq = tv.x * tv.x + tv.y * tv.y + tv.z * tv.z + tv.w * tv.w;
    }
    const int pi = pos_idx[b];
    __syncthreads();   // s_tgt, s_wcnt, mbarrier init visible

    int off = 0, M = 0;
#pragma unroll
    for (int j = 0; j < NWARPS; j++) {
        int c = s_wcnt[j];
        if (j < w) off += c;
        M += c;
    }
    if (mvalid) s_valid[off + __popc(bal & ((1u << lane) - 1u))] = tid;
    __syncthreads();   // s_valid ready

    // --- async double-buffered row streaming ---
    const float* negb = negatives + (size_t)b * (size_t)N * DDIM;
    const float* posr = positives + ((size_t)b * P + pi) * (size_t)DDIM;
    const int R = M + 1;

    const uint32_t buf0 = smem_u32(&s_ring[w][0][0]);
    const uint32_t buf1 = smem_u32(&s_ring[w][1][0]);
    const uint32_t mb0 = smem_u32(&s_mbar[w][0]);
    const uint32_t mb1 = smem_u32(&s_mbar[w][1]);

    // prologue: issue up to 2 rows
    if (lane == 0) {
        int i0 = w;
        if (i0 < R) {
            const float* src = (i0 < M) ? (negb + (size_t)s_valid[i0] * DDIM) : posr;
            mbar_expect_tx(mb0, ROW_BYTES);
            bulk_copy_g2s(buf0, src, ROW_BYTES, mb0);
        }
        int i1 = w + NWARPS;
        if (i1 < R) {
            const float* src = (i1 < M) ? (negb + (size_t)s_valid[i1] * DDIM) : posr;
            mbar_expect_tx(mb1, ROW_BYTES);
            bulk_copy_g2s(buf1, src, ROW_BYTES, mb1);
        }
    }

    uint32_t phase0 = 0, phase1 = 0;
    int st = 0;
    for (int i = w; i < R; i += NWARPS) {
        const uint32_t mb = st ? mb1 : mb0;
        uint32_t& ph = st ? phase1 : phase0;
        mbar_wait(mb, ph);
        ph ^= 1;

        const float4* vrow = (const float4*)&s_ring[w][st][0];
        float dot = 0.0f, q = 0.0f;
#pragma unroll
        for (int k = 0; k < 4; k++) {
            float4 x = vrow[lane + 32 * k];
            float4 t = s_tgt[lane + 32 * k];
            dot = fmaf(x.x, t.x, dot); dot = fmaf(x.y, t.y, dot);
            dot = fmaf(x.z, t.z, dot); dot = fmaf(x.w, t.w, dot);
            q = fmaf(x.x, x.x, q); q = fmaf(x.y, x.y, q);
            q = fmaf(x.z, x.z, q); q = fmaf(x.w, x.w, q);
        }
        dot = warpReduceSum(dot);
        q = warpReduceSum(q);
        if (lane == 0) { s_dot[i] = dot; s_q[i] = q; }

        __syncwarp();  // all lanes done reading buffer before reissue
        const int nx = i + 2 * NWARPS;
        if (lane == 0 && nx < R) {
            const float* src = (nx < M) ? (negb + (size_t)s_valid[nx] * DDIM) : posr;
            mbar_expect_tx(mb, ROW_BYTES);
            bulk_copy_g2s(st ? buf1 : buf0, src, ROW_BYTES, mb);
        }
        st ^= 1;
    }
    __syncthreads();

    // --- epilogue: ||t||, sims, LSE ---
    float tsum = blockReduceSum(tq, s_red);
    if (tid == 0) s_bcast[0] = sqrtf(tsum);
    __syncthreads();
    const float tnorm = s_bcast[0];

    float x = -INFINITY;
    if (tid < M)
        x = (s_dot[tid] / fmaxf(sqrtf(s_q[tid]) * tnorm, COS_EPS)) * TEMP_INV;
    const float pos_sim =
        (s_dot[M] / fmaxf(sqrtf(s_q[M]) * tnorm, COS_EPS)) * TEMP_INV;

    float m = blockReduceMax(fmaxf(x, pos_sim), s_red);
    if (tid == 0) s_bcast[2] = m;
    __syncthreads();
    m = s_bcast[2];
    float e = (x == -INFINITY) ? 0.0f : expf(x - m);
    if (tid == 0) e += expf(pos_sim - m);
    __syncthreads();
    float S = blockReduceSum(e, s_red);

    // --- publish per-anchor loss; last finisher reduces the mean ---
    if (tid == 0) {
        g_loss[b] = logf(S) + m - pos_sim;
        __threadfence();
        unsigned int old = atomicAdd(&g_count, 1u);
        s_islast = (old == (unsigned int)(B - 1));
    }
    __syncthreads();
    if (s_islast) {
        __threadfence();
        float v = 0.0f;
        for (int k = tid; k < B; k += THREADS) v += g_loss[k];
        __syncthreads();
        v = blockReduceSum(v, s_red);
        if (tid == 0) {
            out[0] = v / (float)B;
            g_count = 0;  // reset for next graph replay
        }
    }
}

extern "C" void kernel_launch(void* const* d_in, const int* in_sizes, int n_in,
                              void* d_out, int out_size) {
    const float* target = (const float*)d_in[0];
    const float* positives = (const float*)d_in[1];
    const float* negatives = (const float*)d_in[2];
    const int* pos_idx = (const int*)d_in[3];
    const int* neg_mask = (const int*)d_in[4];
    float* out = (float*)d_out;

    const int B = in_sizes[0] / DDIM;                 // 2048
    const int P = in_sizes[1] / in_sizes[0];          // 16
    const int N = in_sizes[2] / in_sizes[0];          // 128

    ntxent_main_kernel<<<B, THREADS>>>(target, positives, negatives, pos_idx,
                                       neg_mask, out, B, P, N);
}

// round 10
// speedup vs baseline: 1.0048x; 1.0048x over previous
#include <cuda_runtime.h>
#include <math.h>

// NTXentLoss: B=2048, P=16, N=128, D=512 (fp32).
// R10: duty-cycle + occupancy attack (back to plain LDG streaming after the
//      cp.async.bulk experiment regressed).
//   - per-row reduce shortened: 2 shuffle levels only (4 SHFL, ~60cyc), 8
//     partials/row stored to SMEM; full row sums deferred to epilogue
//   - __launch_bounds__(256,6): 6 blocks/SM = 48 warps (75% occ)
//   - valid-only rows + positive row, fused mean

#define DDIM 512
#define D4 (DDIM / 4)
#define THREADS 256
#define NWARPS (THREADS / 32)   // 8
#define TEMP_INV 10.0f
#define COS_EPS 1e-8f

// scratch (no cudaMalloc allowed)
__device__ float g_loss[4096];
__device__ unsigned int g_count = 0;

__device__ __forceinline__ float warpReduceSum(float v) {
#pragma unroll
    for (int o = 16; o; o >>= 1) v += __shfl_down_sync(0xffffffffu, v, o);
    return v;
}

__device__ __forceinline__ float warpReduceMax(float v) {
#pragma unroll
    for (int o = 16; o; o >>= 1) v = fmaxf(v, __shfl_down_sync(0xffffffffu, v, o));
    return v;
}

__device__ __forceinline__ float blockReduceSum(float v, float* sbuf) {
    int lane = threadIdx.x & 31, wid = threadIdx.x >> 5;
    v = warpReduceSum(v);
    if (lane == 0) sbuf[wid] = v;
    __syncthreads();
    v = (threadIdx.x < NWARPS) ? sbuf[threadIdx.x] : 0.0f;
    if (wid == 0) {
#pragma unroll
        for (int o = NWARPS / 2; o; o >>= 1) v += __shfl_down_sync(0xffffffffu, v, o);
    }
    return v;
}

__device__ __forceinline__ float blockReduceMax(float v, float* sbuf) {
    int lane = threadIdx.x & 31, wid = threadIdx.x >> 5;
    v = warpReduceMax(v);
    if (lane == 0) sbuf[wid] = v;
    __syncthreads();
    v = (threadIdx.x < NWARPS) ? sbuf[threadIdx.x] : -INFINITY;
    if (wid == 0) {
#pragma unroll
        for (int o = NWARPS / 2; o; o >>= 1) v = fmaxf(v, __shfl_down_sync(0xffffffffu, v, o));
    }
    return v;
}

__global__ void __launch_bounds__(THREADS, 6)
ntxent_main_kernel(const float* __restrict__ target,
                   const float* __restrict__ positives,
                   const float* __restrict__ negatives,
                   const int* __restrict__ pos_idx,
                   const int* __restrict__ neg_mask,
                   float* __restrict__ out,
                   int B, int P, int N) {
    const int b = blockIdx.x;
    const int tid = threadIdx.x;
    const int lane = tid & 31;
    const int w = tid >> 5;

    __shared__ float4 s_tgt[D4];          // 2KB target row
    __shared__ float s_pdot[130][9];      // 8 partial dots per row (padded)
    __shared__ float s_pq[130][9];        // 8 partial sq-norms per row
    __shared__ int   s_valid[132];
    __shared__ int   s_wcnt[NWARPS];
    __shared__ float s_red[NWARPS];
    __shared__ float s_bcast[4];          // [0]=||t||, [1]=pos_sim, [2]=max
    __shared__ int   s_islast;

    // --- compact valid negative indices (deterministic prefix via ballot) ---
    int mvalid = 0;
    if (tid < N) mvalid = (neg_mask[(size_t)b * N + tid] != 0);
    unsigned bal = __ballot_sync(0xffffffffu, mvalid);
    if (lane == 0) s_wcnt[w] = __popc(bal);

    // --- target row -> SMEM; |t|^2 partial in a register ---
    float tq = 0.0f;
    if (tid < D4) {
        float4 tv = ((const float4*)(target + (size_t)b * DDIM))[tid];
        s_tgt[tid] = tv;
        tq = tv.x * tv.x + tv.y * tv.y + tv.z * tv.z + tv.w * tv.w;
    }
    const int pi = pos_idx[b];
    __syncthreads();   // s_tgt + s_wcnt ready

    int off = 0, M = 0;
#pragma unroll
    for (int j = 0; j < NWARPS; j++) {
        int c = s_wcnt[j];
        if (j < w) off += c;
        M += c;
    }
    if (mvalid) s_valid[off + __popc(bal & ((1u << lane) - 1u))] = tid;
    __syncthreads();   // s_valid ready

    // --- stream rows: valid negatives + positive as row M ---
    const float4* negb = (const float4*)(negatives + (size_t)b * (size_t)N * DDIM);
    const float4* posr = (const float4*)(positives + ((size_t)b * P + pi) * (size_t)DDIM);
    const int R = M + 1;

    for (int i = w; i < R; i += NWARPS) {
        const float4* v = (i < M) ? (negb + (size_t)s_valid[i] * D4) : posr;
        float dot = 0.0f, q = 0.0f;
#pragma unroll
        for (int k = 0; k < 4; k++) {    // 4 front-batched LDG.128
            float4 x = v[lane + 32 * k];
            float4 t = s_tgt[lane + 32 * k];
            dot = fmaf(x.x, t.x, dot); dot = fmaf(x.y, t.y, dot);
            dot = fmaf(x.z, t.z, dot); dot = fmaf(x.w, t.w, dot);
            q = fmaf(x.x, x.x, q); q = fmaf(x.y, x.y, q);
            q = fmaf(x.z, x.z, q); q = fmaf(x.w, x.w, q);
        }
        // SHORT reduce: 2 levels only -> lanes 0,4,8,... hold 4-lane sums
        dot += __shfl_down_sync(0xffffffffu, dot, 1);
        q   += __shfl_down_sync(0xffffffffu, q, 1);
        dot += __shfl_down_sync(0xffffffffu, dot, 2);
        q   += __shfl_down_sync(0xffffffffu, q, 2);
        if ((lane & 3) == 0) {
            s_pdot[i][lane >> 2] = dot;
            s_pq[i][lane >> 2] = q;
        }
    }
    __syncthreads();

    // --- epilogue: ||t||, per-row sums, LSE ---
    float tsum = blockReduceSum(tq, s_red);
    if (tid == 0) s_bcast[0] = sqrtf(tsum);
    __syncthreads();
    const float tnorm = s_bcast[0];

    float x = -INFINITY;
    if (tid < R) {
        float dot = 0.0f, q = 0.0f;
#pragma unroll
        for (int j = 0; j < 8; j++) {
            dot += s_pdot[tid][j];
            q += s_pq[tid][j];
        }
        float sim = (dot / fmaxf(sqrtf(q) * tnorm, COS_EPS)) * TEMP_INV;
        if (tid < M) x = sim;
        else s_bcast[1] = sim;   // tid == M: positive logit
    }
    __syncthreads();
    const float pos_sim = s_bcast[1];

    float m = blockReduceMax(fmaxf(x, pos_sim), s_red);
    if (tid == 0) s_bcast[2] = m;
    __syncthreads();
    m = s_bcast[2];
    float e = (x == -INFINITY) ? 0.0f : expf(x - m);
    if (tid == 0) e += expf(pos_sim - m);   // fold positive term
    __syncthreads();  // protect s_red reuse
    float S = blockReduceSum(e, s_red);

    // --- publish per-anchor loss; last finisher reduces the mean ---
    if (tid == 0) {
        g_loss[b] = logf(S) + m - pos_sim;
        __threadfence();
        unsigned int old = atomicAdd(&g_count, 1u);
        s_islast = (old == (unsigned int)(B - 1));
    }
    __syncthreads();
    if (s_islast) {
        __threadfence();
        float v = 0.0f;
        for (int k = tid; k < B; k += THREADS) v += g_loss[k];
        __syncthreads();  // s_red safe to reuse
        v = blockReduceSum(v, s_red);
        if (tid == 0) {
            out[0] = v / (float)B;
            g_count = 0;  // reset for next graph replay
        }
    }
}

extern "C" void kernel_launch(void* const* d_in, const int* in_sizes, int n_in,
                              void* d_out, int out_size) {
    const float* target = (const float*)d_in[0];
    const float* positives = (const float*)d_in[1];
    const float* negatives = (const float*)d_in[2];
    const int* pos_idx = (const int*)d_in[3];
    const int* neg_mask = (const int*)d_in[4];
    float* out = (float*)d_out;

    const int B = in_sizes[0] / DDIM;                 // 2048
    const int P = in_sizes[1] / in_sizes[0];          // 16
    const int N = in_sizes[2] / in_sizes[0];          // 128

    ntxent_main_kernel<<<B, THREADS>>>(target, positives, negatives, pos_idx,
                                       neg_mask, out, B, P, N);
}